// round 17
// baseline (speedup 1.0000x reference)
#include <cuda_runtime.h>
#include <cuda_fp16.h>
#include <math.h>

// Problem dims
#define Vv 32000
#define Ee 512
#define Hh 512
#define Bb 16
#define Tt 128
#define Ss 512

constexpr int BT   = Bb * Tt;          // 2048
constexpr int G4H  = 4 * Hh;           // 2048
constexpr int KIN  = Ee + Hh;          // 1024
constexpr int AIN  = 2 * Hh + Ee;      // 1536
constexpr long OUT0 = (long)BT * Vv;
constexpr long OUT1 = (long)BT * AIN;
constexpr long OUT2 = BT;
constexpr long BSH  = (long)Bb * Ss * Hh;

// ---------------- scratch (device globals) --------------------------------
__device__ float g_Gx[BT * G4H];
__device__ float g_bsum[G4H];
__device__ float g_hbuf[2][Bb * Hh];
__device__ float g_cbuf[Bb * Hh];
__device__ float g_lohtb[BT * 1024];      // fp32 [ lstm_out | h_t_bar ] (combine)
__device__ float g_att[BT * Ss];          // fp32 logits -> softmax input
__device__ int   g_bar;
// fp16 operands (A-side: contiguous halves = k-pairs for free)
__device__ __half g_lin_h[BT * KIN];          // lstm_input
__device__ __half g_attn_h[BT * AIN];         // attention_input
__device__ __half g_soft_h[BT * Ss];          // softmax output
__device__ __half g_loh_h[BT * 1024];         // [ lstm_out | h_t_bar ] halves
// fp16 B-side packs (half2 k-pairs, [K/2][N])
__device__ unsigned g_Wih_p[(KIN / 2) * G4H];
__device__ unsigned g_Watt_p[(AIN / 2) * Ss];
__device__ unsigned g_Walign_p[(1024 / 2) * Hh];
__device__ unsigned g_enc_p[Bb * (Ss / 2) * Hh];
// output GEMM operands
__device__ unsigned g_Ap[BT * (Hh / 2)];             // out_pre half2 pairs
__device__ unsigned g_Wp[(long)(Hh / 2) * Vv];       // W_out half2 pairs

// ---------------- fused prep kernel ----------------------------------------
__global__ void k_prep(const int* __restrict__ x,
                       const float* __restrict__ h0,
                       const float* __restrict__ c0,
                       const float* __restrict__ emb,
                       const float* __restrict__ b_ih,
                       const float* __restrict__ b_hh,
                       float* __restrict__ out, int wo, int wt) {
    int i = blockIdx.x * 256 + threadIdx.x;
    if (i == 0) g_bar = 0;
    if (i < G4H) g_bsum[i] = b_ih[i] + b_hh[i];
    if (i < Bb * Hh) { g_hbuf[0][i] = h0[i]; g_cbuf[i] = c0[i]; }
    if (i < BT && wt) out[OUT0 + OUT1 + i] = (float)((Ss / Tt) * (i % Tt));
    if (i >= BT * KIN) return;
    int bt = i / KIN, c = i % KIN;
    int b = bt / Tt;
    float v;
    if (c < Hh) v = h0[b * Hh + c] + c0[b * Hh + c];
    else        v = emb[(long)x[bt] * Ee + (c - Hh)];
    g_lin_h[i] = __float2half(v);
    long ao = (long)bt * AIN + Hh + c;     // attention_input cols 512..1535
    g_attn_h[ao] = __float2half(v);
    if (wo) out[OUT0 + ao] = v;
}

// pack W_ih [4H][KIN] fp32 -> g_Wih_p [KIN/2][4H] half2 (transpose + pair)
__global__ void k_pack_wih(const float* __restrict__ W) {
    __shared__ float t[32][33];
    int k0 = blockIdx.x * 32;   // over KIN
    int n0 = blockIdx.y * 32;   // over 4H
    #pragma unroll
    for (int i = 0; i < 32; i += 8)
        t[threadIdx.y + i][threadIdx.x] = W[(long)(n0 + threadIdx.y + i) * KIN + k0 + threadIdx.x];
    __syncthreads();
    #pragma unroll
    for (int j = 0; j < 2; j++) {
        int kk = threadIdx.y + j * 8;          // k2-local 0..15
        __half2 h = __floats2half2_rn(t[threadIdx.x][2 * kk], t[threadIdx.x][2 * kk + 1]);
        g_Wih_p[(long)(k0 / 2 + kk) * G4H + n0 + threadIdx.x] = *(unsigned*)&h;
    }
}

// pack generic B [K][N] fp32 -> dst [K/2][N] half2 (coalesced)
__global__ void k_packB(const float* __restrict__ src, unsigned* __restrict__ dst,
                        int K2, int N) {
    long i = (long)blockIdx.x * 256 + threadIdx.x;
    if (i >= (long)K2 * N) return;
    int k2 = (int)(i / N), n = (int)(i % N);
    __half2 h = __floats2half2_rn(src[(long)(2 * k2) * N + n],
                                  src[(long)(2 * k2 + 1) * N + n]);
    dst[i] = *(unsigned*)&h;
}

// pack encoder: (eo + eo[BSH]) [16][S][H] -> g_enc_p [16][S/2][H] half2
__global__ void k_pack_enc(const float* __restrict__ eo) {
    long i = (long)blockIdx.x * 256 + threadIdx.x;
    const long TOT = (long)Bb * (Ss / 2) * Hh;
    if (i >= TOT) return;
    long b = i / ((Ss / 2) * Hh);
    long r = i % ((Ss / 2) * Hh);
    int s2 = (int)(r / Hh), h = (int)(r % Hh);
    long o0 = b * Ss * Hh + (long)(2 * s2) * Hh + h;
    long o1 = o0 + Hh;
    __half2 p = __floats2half2_rn(eo[o0] + eo[BSH + o0], eo[o1] + eo[BSH + o1]);
    g_enc_p[i] = *(unsigned*)&p;
}

// pack W_out [512][32000] fp32 -> g_Wp [256][32000] half2 (k-pairs)
__global__ void k_pack_wout(const float* __restrict__ W) {
    long i = (long)blockIdx.x * 256 + threadIdx.x;   // over 256*8000 float4-groups
    if (i >= 256L * 8000) return;
    int k2 = (int)(i / 8000), c = (int)(i % 8000);
    const float4 r0 = *(const float4*)&W[(long)(2 * k2) * Vv + c * 4];
    const float4 r1 = *(const float4*)&W[(long)(2 * k2 + 1) * Vv + c * 4];
    uint4 u;
    __half2 h;
    h = __floats2half2_rn(r0.x, r1.x); u.x = *(unsigned*)&h;
    h = __floats2half2_rn(r0.y, r1.y); u.y = *(unsigned*)&h;
    h = __floats2half2_rn(r0.z, r1.z); u.z = *(unsigned*)&h;
    h = __floats2half2_rn(r0.w, r1.w); u.w = *(unsigned*)&h;
    *(uint4*)&g_Wp[i * 4] = u;
}

// ---------------- MMA helper -----------------------------------------------
#define MMA_F16(ACC, AF, B0, B1)                                               \
    asm volatile(                                                              \
        "mma.sync.aligned.m16n8k16.row.col.f32.f16.f16.f32 "                   \
        "{%0,%1,%2,%3}, {%4,%5,%6,%7}, {%8,%9}, {%0,%1,%2,%3};"                \
        : "+f"((ACC)[0]), "+f"((ACC)[1]), "+f"((ACC)[2]), "+f"((ACC)[3])       \
        : "r"((AF)[0]), "r"((AF)[1]), "r"((AF)[2]), "r"((AF)[3]),              \
          "r"(B0), "r"(B1))

// ---------------- generic fp16 GEMM, 128x128 tile, K-tile 32 ---------------
// A: [M][ldk2] half2 k-pairs; B: [K/2][N] half2 k-pairs (+ per-y-tile stride
// sBy for the batched bmm); C fp32.
// MODE 0: C = acc + bias
// MODE 1: h_t_bar — C fp32 (base g_lohtb+512, ldc 1024) + halves to g_loh_h
// MODE 2: combine — out_pre = lo + htb*sigmoid(acc+bias) -> g_Ap half2
template<int MODE>
__global__ void __launch_bounds__(256) hgemm_k(
        const unsigned* __restrict__ A, int ldk2,
        const unsigned* __restrict__ Bm, long sBy, int N,
        const float* __restrict__ bias,
        float* __restrict__ C, int ldc, int K) {
    __shared__ unsigned As[2][128 * 20];
    __shared__ unsigned Bs[2][16 * 136];
    Bm += (long)blockIdx.y * sBy;
    const int m0 = blockIdx.y * 128, n0 = blockIdx.x * 128;
    const int tid = threadIdx.x;
    const int lane = tid & 31, wid = tid >> 5;
    const int warpM = wid >> 2, warpN = wid & 3;
    const int gid = lane >> 2, tig = lane & 3;
    const int ar = tid >> 2, aq = tid & 3;
    const int br = tid >> 5, bc = tid & 31;
    const uint4* A4 = (const uint4*)A; const int lda4 = ldk2 >> 2;
    const uint4* B4 = (const uint4*)Bm; const int ldb4 = N >> 2;

    float acc[4][4][4] = {};
    const int NT = K / 32;

    uint4 ra[2], rb[2];
    #pragma unroll
    for (int i = 0; i < 2; i++) {
        ra[i] = A4[(long)(m0 + ar + i * 64) * lda4 + aq];
        rb[i] = B4[(long)(br + i * 8) * ldb4 + (n0 >> 2) + bc];
    }
    #pragma unroll
    for (int i = 0; i < 2; i++) {
        *(uint4*)&As[0][(ar + i * 64) * 20 + aq * 4] = ra[i];
        *(uint4*)&Bs[0][(br + i * 8) * 136 + bc * 4] = rb[i];
    }
    __syncthreads();
    if (NT > 1) {
        #pragma unroll
        for (int i = 0; i < 2; i++) {
            ra[i] = A4[(long)(m0 + ar + i * 64) * lda4 + 4 + aq];
            rb[i] = B4[(long)(16 + br + i * 8) * ldb4 + (n0 >> 2) + bc];
        }
    }

    for (int kt = 0; kt < NT; kt++) {
        const unsigned* Ac = As[kt & 1];
        const unsigned* Bc = Bs[kt & 1];
        #pragma unroll
        for (int ks = 0; ks < 2; ks++) {
            const int k2o = ks * 8;
            unsigned af[4][4], bf[4][2];
            #pragma unroll
            for (int mi = 0; mi < 4; mi++) {
                int mm = warpM * 64 + mi * 16;
                af[mi][0] = Ac[(mm + gid) * 20 + k2o + tig];
                af[mi][1] = Ac[(mm + 8 + gid) * 20 + k2o + tig];
                af[mi][2] = Ac[(mm + gid) * 20 + k2o + 4 + tig];
                af[mi][3] = Ac[(mm + 8 + gid) * 20 + k2o + 4 + tig];
            }
            #pragma unroll
            for (int ni = 0; ni < 4; ni++) {
                int nn = warpN * 32 + ni * 8;
                bf[ni][0] = Bc[(k2o + tig) * 136 + nn + gid];
                bf[ni][1] = Bc[(k2o + 4 + tig) * 136 + nn + gid];
            }
            #pragma unroll
            for (int mi = 0; mi < 4; mi++)
                #pragma unroll
                for (int ni = 0; ni < 4; ni++)
                    MMA_F16(acc[mi][ni], af[mi], bf[ni][0], bf[ni][1]);
        }
        if (kt + 1 < NT) {
            unsigned* An = As[(kt + 1) & 1];
            unsigned* Bn = Bs[(kt + 1) & 1];
            #pragma unroll
            for (int i = 0; i < 2; i++) {
                *(uint4*)&An[(ar + i * 64) * 20 + aq * 4] = ra[i];
                *(uint4*)&Bn[(br + i * 8) * 136 + bc * 4] = rb[i];
            }
            if (kt + 2 < NT) {
                #pragma unroll
                for (int i = 0; i < 2; i++) {
                    ra[i] = A4[(long)(m0 + ar + i * 64) * lda4 + (kt + 2) * 4 + aq];
                    rb[i] = B4[(long)((kt + 2) * 16 + br + i * 8) * ldb4 + (n0 >> 2) + bc];
                }
            }
        }
        __syncthreads();
    }

    #pragma unroll
    for (int mi = 0; mi < 4; mi++) {
        int r = m0 + warpM * 64 + mi * 16 + gid;
        #pragma unroll
        for (int ni = 0; ni < 4; ni++) {
            int cc = n0 + warpN * 32 + ni * 8 + tig * 2;
            if (MODE == 0) {
                float b0v = bias[cc], b1v = bias[cc + 1];
                float2 v0, v1;
                v0.x = acc[mi][ni][0] + b0v; v0.y = acc[mi][ni][1] + b1v;
                v1.x = acc[mi][ni][2] + b0v; v1.y = acc[mi][ni][3] + b1v;
                *(float2*)&C[(long)r * ldc + cc] = v0;
                *(float2*)&C[(long)(r + 8) * ldc + cc] = v1;
            } else if (MODE == 1) {
                float2 v0, v1;
                v0.x = acc[mi][ni][0]; v0.y = acc[mi][ni][1];
                v1.x = acc[mi][ni][2]; v1.y = acc[mi][ni][3];
                *(float2*)&C[(long)r * ldc + cc] = v0;
                *(float2*)&C[(long)(r + 8) * ldc + cc] = v1;
                __half2 h0 = __floats2half2_rn(v0.x, v0.y);
                __half2 h1 = __floats2half2_rn(v1.x, v1.y);
                *(__half2*)&g_loh_h[(long)r * 1024 + 512 + cc] = h0;
                *(__half2*)&g_loh_h[(long)(r + 8) * 1024 + 512 + cc] = h1;
            } else {
                float b0v = bias[cc], b1v = bias[cc + 1];
                float vv[2][2];
                float a00 = 1.0f / (1.0f + __expf(-(acc[mi][ni][0] + b0v)));
                float a01 = 1.0f / (1.0f + __expf(-(acc[mi][ni][1] + b1v)));
                float a10 = 1.0f / (1.0f + __expf(-(acc[mi][ni][2] + b0v)));
                float a11 = 1.0f / (1.0f + __expf(-(acc[mi][ni][3] + b1v)));
                float2 lo0 = *(float2*)&g_lohtb[(long)r * 1024 + cc];
                float2 ht0 = *(float2*)&g_lohtb[(long)r * 1024 + 512 + cc];
                float2 lo1 = *(float2*)&g_lohtb[(long)(r + 8) * 1024 + cc];
                float2 ht1 = *(float2*)&g_lohtb[(long)(r + 8) * 1024 + 512 + cc];
                vv[0][0] = lo0.x + ht0.x * a00; vv[0][1] = lo0.y + ht0.y * a01;
                vv[1][0] = lo1.x + ht1.x * a10; vv[1][1] = lo1.y + ht1.y * a11;
                #pragma unroll
                for (int q = 0; q < 2; q++) {
                    __half2 h = __floats2half2_rn(vv[q][0], vv[q][1]);
                    g_Ap[(long)(r + q * 8) * (Hh / 2) + (cc >> 1)] = *(unsigned*)&h;
                }
            }
        }
    }
}

// ---------------- fp16 WIDE GEMM: 128x256, k-tile 32, m16n8k16 -------------
constexpr int HAPAD = 20;
constexpr int HBPAD = 264;
constexpr int HSM_A = 128 * HAPAD;
constexpr int HSM_B = 16 * HBPAD;
constexpr int HSMEM_BYTES = (2 * HSM_A + 2 * HSM_B) * 4;   // 54272

__global__ void __launch_bounds__(256) tgemm_wide_h_k(
        const float* __restrict__ bias, float* __restrict__ C) {
    extern __shared__ unsigned smh[];
    unsigned* As = smh;
    unsigned* Bs = smh + 2 * HSM_A;
    const int m0 = blockIdx.y * 128, n0 = blockIdx.x * 256;
    const int tid = threadIdx.x;
    const int lane = tid & 31, wid = tid >> 5;
    const int warpM = wid >> 2, warpN = wid & 3;
    const int gid = lane >> 2, tig = lane & 3;
    const int ar = tid >> 2, aq = tid & 3;
    const int br = tid >> 6, bc = tid & 63;

    const uint4* gA = (const uint4*)g_Ap;
    const uint4* gB = (const uint4*)g_Wp;

    float acc[4][8][4] = {};
    const int NT = Hh / 32;

    uint4 ra[2], rb[4];
    #pragma unroll
    for (int i = 0; i < 2; i++)
        ra[i] = gA[(long)(m0 + ar + i * 64) * 64 + aq];
    #pragma unroll
    for (int i = 0; i < 4; i++)
        rb[i] = gB[(long)(br + i * 4) * 8000 + (n0 >> 2) + bc];
    #pragma unroll
    for (int i = 0; i < 2; i++)
        *(uint4*)&As[(ar + i * 64) * HAPAD + aq * 4] = ra[i];
    #pragma unroll
    for (int i = 0; i < 4; i++)
        *(uint4*)&Bs[(br + i * 4) * HBPAD + bc * 4] = rb[i];
    __syncthreads();
    #pragma unroll
    for (int i = 0; i < 2; i++)
        ra[i] = gA[(long)(m0 + ar + i * 64) * 64 + 4 + aq];
    #pragma unroll
    for (int i = 0; i < 4; i++)
        rb[i] = gB[(long)(16 + br + i * 4) * 8000 + (n0 >> 2) + bc];

    for (int kt = 0; kt < NT; kt++) {
        const unsigned* Ac = As + (kt & 1) * HSM_A;
        const unsigned* Bc = Bs + (kt & 1) * HSM_B;
        #pragma unroll
        for (int ks = 0; ks < 2; ks++) {
            const int k2o = ks * 8;
            unsigned af[4][4], bf[8][2];
            #pragma unroll
            for (int mi = 0; mi < 4; mi++) {
                int mm = warpM * 64 + mi * 16;
                af[mi][0] = Ac[(mm + gid) * HAPAD + k2o + tig];
                af[mi][1] = Ac[(mm + 8 + gid) * HAPAD + k2o + tig];
                af[mi][2] = Ac[(mm + gid) * HAPAD + k2o + 4 + tig];
                af[mi][3] = Ac[(mm + 8 + gid) * HAPAD + k2o + 4 + tig];
            }
            #pragma unroll
            for (int ni = 0; ni < 8; ni++) {
                int nn = warpN * 64 + ni * 8;
                bf[ni][0] = Bc[(k2o + tig) * HBPAD + nn + gid];
                bf[ni][1] = Bc[(k2o + 4 + tig) * HBPAD + nn + gid];
            }
            #pragma unroll
            for (int mi = 0; mi < 4; mi++)
                #pragma unroll
                for (int ni = 0; ni < 8; ni++)
                    MMA_F16(acc[mi][ni], af[mi], bf[ni][0], bf[ni][1]);
        }
        if (kt + 1 < NT) {
            unsigned* An = As + ((kt + 1) & 1) * HSM_A;
            unsigned* Bn = Bs + ((kt + 1) & 1) * HSM_B;
            #pragma unroll
            for (int i = 0; i < 2; i++)
                *(uint4*)&An[(ar + i * 64) * HAPAD + aq * 4] = ra[i];
            #pragma unroll
            for (int i = 0; i < 4; i++)
                *(uint4*)&Bn[(br + i * 4) * HBPAD + bc * 4] = rb[i];
            if (kt + 2 < NT) {
                int k40 = (kt + 2) * 4;
                int k20 = (kt + 2) * 16;
                #pragma unroll
                for (int i = 0; i < 2; i++)
                    ra[i] = gA[(long)(m0 + ar + i * 64) * 64 + k40 + aq];
                #pragma unroll
                for (int i = 0; i < 4; i++)
                    rb[i] = gB[(long)(k20 + br + i * 4) * 8000 + (n0 >> 2) + bc];
            }
        }
        __syncthreads();
    }

    #pragma unroll
    for (int mi = 0; mi < 4; mi++) {
        int r = m0 + warpM * 64 + mi * 16 + gid;
        #pragma unroll
        for (int ni = 0; ni < 8; ni++) {
            int cc = n0 + warpN * 64 + ni * 8 + tig * 2;
            float b0v = bias[cc], b1v = bias[cc + 1];
            float2 v0, v1;
            v0.x = acc[mi][ni][0] + b0v; v0.y = acc[mi][ni][1] + b1v;
            v1.x = acc[mi][ni][2] + b0v; v1.y = acc[mi][ni][3] + b1v;
            *(float2*)&C[(long)r * Vv + cc] = v0;
            *(float2*)&C[(long)(r + 8) * Vv + cc] = v1;
        }
    }
}

// ---------------- persistent LSTM (latency-diet barrier) -------------------
__device__ __forceinline__ int swz(int row, int s4) {
    return row * 128 + (s4 ^ ((row & 12) >> 1));
}
__device__ __forceinline__ float tanh_apx(float x) {
    float y;
    asm("tanh.approx.f32 %0, %1;" : "=f"(y) : "f"(x));
    return y;
}

__global__ void __launch_bounds__(256) lstm_persist_k(const int* __restrict__ xlen,
                                                      const float* __restrict__ W_hh,
                                                      float* __restrict__ oat, int wo) {
    extern __shared__ float sm[];
    float* ws  = sm;
    float* hs  = sm + 8192;
    float* red = sm + 16384;

    const int tid = threadIdx.x;
    const int k0  = blockIdx.x * 4;
    const int sc = tid >> 4, bt = (tid >> 2) & 3, jt = tid & 3;
    float4* ws4 = (float4*)ws;
    float4* hs4 = (float4*)hs;

    {
        int r = tid >> 4, c16 = tid & 15;
        int g = r >> 2, dk = r & 3;
        const float4* src = (const float4*)&W_hh[(long)(g * 512 + k0 + dk) * 512];
        #pragma unroll
        for (int i = 0; i < 8; i++) {
            int s4 = c16 + i * 16;
            ws4[swz(r, s4)] = src[s4];
        }
    }

    int ub = tid >> 2, udk = tid & 3;
    float creg = 0.0f; int xl = 0;
    if (tid < 64) {
        creg = g_cbuf[ub * 512 + k0 + udk];
        xl   = xlen[ub];
    }

    const int hxor = bt * 2;
    const int wxor = jt * 2;

    int* barp;
    asm("cvta.global.u64 %0, g_bar;" : "=l"(barp));

    for (int t = 0; t < Tt; t++) {
        const float4* hin = (const float4*)g_hbuf[t & 1];
        #pragma unroll
        for (int i = 0; i < 8; i++) {
            int j = tid + i * 256;
            int row = j >> 7, s4 = j & 127;
            hs4[swz(row, s4)] = __ldcg(&hin[j]);
        }
        float gxr[4];
        if (tid < 64) {
            #pragma unroll
            for (int g = 0; g < 4; g++)
                gxr[g] = g_Gx[(long)(ub * Tt + t) * G4H + g * 512 + k0 + udk];
        }
        __syncthreads();

        float acc[4][4] = {};
        #pragma unroll
        for (int i = 0; i < 8; i++) {
            int s4b = sc + (i << 4);
            float4 hv[4], wv[4];
            #pragma unroll
            for (int bi = 0; bi < 4; bi++)
                hv[bi] = hs4[(bt * 4 + bi) * 128 + (s4b ^ hxor)];
            #pragma unroll
            for (int ji = 0; ji < 4; ji++)
                wv[ji] = ws4[(jt * 4 + ji) * 128 + (s4b ^ wxor)];
            #pragma unroll
            for (int bi = 0; bi < 4; bi++)
                #pragma unroll
                for (int ji = 0; ji < 4; ji++)
                    acc[bi][ji] += hv[bi].x * wv[ji].x + hv[bi].y * wv[ji].y +
                                   hv[bi].z * wv[ji].z + hv[bi].w * wv[ji].w;
        }
        {
            int perm = bt * 4 + jt;
            #pragma unroll
            for (int bi = 0; bi < 4; bi++)
                #pragma unroll
                for (int ji = 0; ji < 4; ji++) {
                    int o = (bt * 4 + bi) * 16 + jt * 4 + ji;
                    red[o * 16 + (sc ^ perm)] = acc[bi][ji];
                }
        }
        __syncthreads();

        if (tid < 64) {
            int k = k0 + udk;
            float gate[4];
            #pragma unroll
            for (int g = 0; g < 4; g++) {
                int o = ub * 16 + g * 4 + udk;
                int perm = (o >> 6) * 4 + ((o >> 2) & 3);
                float s = 0.0f;
                #pragma unroll
                for (int scx = 0; scx < 16; scx++) s += red[o * 16 + (scx ^ perm)];
                gate[g] = gxr[g] + s;
            }
            float iv = 1.0f / (1.0f + __expf(-gate[0]));
            float fv = 1.0f / (1.0f + __expf(-gate[1]));
            float gg = tanh_apx(gate[2]);
            float ov = 1.0f / (1.0f + __expf(-gate[3]));
            float cn = fv * creg + iv * gg;
            float hn = ov * tanh_apx(cn);
            bool valid = (t < xl);
            creg = valid ? cn : creg;
            float hold = hs[swz(ub, k >> 2) * 4 + (k & 3)];
            float heff = valid ? hn : hold;
            __stcg(&g_hbuf[(t + 1) & 1][ub * 512 + k], heff);
            float lo = valid ? hn : 0.0f;
            long row = (long)(ub * Tt + t);
            g_lohtb[row * 1024 + k] = lo;                     // fp32 (combine)
            __half lh = __float2half(lo);
            g_loh_h[row * 1024 + k] = lh;                     // align A
            g_attn_h[row * AIN + k] = lh;                     // attn A cols 0..511
            if (wo) oat[row * AIN + k] = lo;                  // output slot 1
        }
        __syncthreads();

        if (t + 1 < Tt) {
            if (tid == 0) {
                asm volatile("fence.acq_rel.gpu;" ::: "memory");
                atomicAdd(barp, 1);
                int target = 128 * (t + 1);
                int v;
                do {
                    asm volatile("ld.global.acquire.gpu.b32 %0, [%1];"
                                 : "=r"(v) : "l"(barp) : "memory");
                } while (v < target);
            }
            __syncthreads();
        }
    }
}

// ---------------- row softmax over S=512 (+ half output for bmm A) ---------
__global__ void softmax_k() {
    __shared__ float red[8];
    float* p = g_att + (long)blockIdx.x * Ss;
    __half* ph = g_soft_h + (long)blockIdx.x * Ss;
    int tid = threadIdx.x;
    float m = -1e30f;
    for (int i = tid; i < Ss; i += 256) m = fmaxf(m, p[i]);
    #pragma unroll
    for (int o = 16; o; o >>= 1) m = fmaxf(m, __shfl_xor_sync(~0u, m, o));
    if ((tid & 31) == 0) red[tid >> 5] = m;
    __syncthreads();
    if (tid == 0) { float v = red[0]; for (int i = 1; i < 8; i++) v = fmaxf(v, red[i]); red[0] = v; }
    __syncthreads();
    m = red[0];
    __syncthreads();
    float s = 0.0f;
    for (int i = tid; i < Ss; i += 256) { float e = __expf(p[i] - m); p[i] = e; s += e; }
    #pragma unroll
    for (int o = 16; o; o >>= 1) s += __shfl_xor_sync(~0u, s, o);
    if ((tid & 31) == 0) red[tid >> 5] = s;
    __syncthreads();
    if (tid == 0) { float v = 0.0f; for (int i = 0; i < 8; i++) v += red[i]; red[0] = v; }
    __syncthreads();
    float inv = 1.0f / red[0];
    for (int i = tid; i < Ss; i += 256) {
        float v = p[i] * inv;
        p[i] = v;
        ph[i] = __float2half(v);
    }
}

// ---------------- host launcher --------------------------------------------
extern "C" void kernel_launch(void* const* d_in, const int* in_sizes, int n_in,
                              void* d_out, int out_size) {
    const int*   x       = (const int*)  d_in[0];
    const int*   xlen    = (const int*)  d_in[1];
    const float* h0      = (const float*)d_in[2];
    const float* c0      = (const float*)d_in[3];
    const float* eo      = (const float*)d_in[4];
    const float* emb     = (const float*)d_in[5];
    const float* W_att   = (const float*)d_in[6];
    const float* b_att   = (const float*)d_in[7];
    const float* W_ih    = (const float*)d_in[8];
    const float* W_hh    = (const float*)d_in[9];
    const float* b_ih    = (const float*)d_in[10];
    const float* b_hh    = (const float*)d_in[11];
    const float* W_align = (const float*)d_in[12];
    const float* b_align = (const float*)d_in[13];
    const float* W_out   = (const float*)d_in[14];
    const float* b_out   = (const float*)d_in[15];
    float* out = (float*)d_out;

    void *p_gx, *p_lohtb, *p_att, *p_bsum;
    void *p_linh, *p_attnh, *p_softh, *p_lohh;
    void *p_wihp, *p_wattp, *p_walignp, *p_encp;
    cudaGetSymbolAddress(&p_gx,     g_Gx);
    cudaGetSymbolAddress(&p_lohtb,  g_lohtb);
    cudaGetSymbolAddress(&p_att,    g_att);
    cudaGetSymbolAddress(&p_bsum,   g_bsum);
    cudaGetSymbolAddress(&p_linh,   g_lin_h);
    cudaGetSymbolAddress(&p_attnh,  g_attn_h);
    cudaGetSymbolAddress(&p_softh,  g_soft_h);
    cudaGetSymbolAddress(&p_lohh,   g_loh_h);
    cudaGetSymbolAddress(&p_wihp,   g_Wih_p);
    cudaGetSymbolAddress(&p_wattp,  g_Watt_p);
    cudaGetSymbolAddress(&p_walignp, g_Walign_p);
    cudaGetSymbolAddress(&p_encp,   g_enc_p);
    float* gx    = (float*)p_gx;
    float* lohtb = (float*)p_lohtb;
    float* att   = (float*)p_att;
    float* bsum  = (float*)p_bsum;
    const unsigned* linh  = (const unsigned*)p_linh;
    const unsigned* attnh = (const unsigned*)p_attnh;
    const unsigned* softh = (const unsigned*)p_softh;
    const unsigned* lohh  = (const unsigned*)p_lohh;
    const unsigned* wihp  = (const unsigned*)p_wihp;
    const unsigned* wattp = (const unsigned*)p_wattp;
    const unsigned* walignp = (const unsigned*)p_walignp;
    const unsigned* encp  = (const unsigned*)p_encp;
    unsigned* wattp_w   = (unsigned*)p_wattp;
    unsigned* walignp_w = (unsigned*)p_walignp;

    static bool attr_done = false;
    if (!attr_done) {
        cudaFuncSetAttribute(lstm_persist_k,
                             cudaFuncAttributeMaxDynamicSharedMemorySize, 84 * 1024);
        cudaFuncSetAttribute(tgemm_wide_h_k,
                             cudaFuncAttributeMaxDynamicSharedMemorySize, HSMEM_BYTES);
        attr_done = true;
    }

    int wo = ((long)out_size >= OUT0 + OUT1) ? 1 : 0;
    int wt = ((long)out_size >= OUT0 + OUT1 + OUT2) ? 1 : 0;

    // (1) fused prep (lstm_input + attn_in halves)
    k_prep<<<(BT * KIN + 255) / 256, 256>>>(x, h0, c0, emb, b_ih, b_hh, out, wo, wt);

    // (2) pack W_ih -> [KIN/2][4H] half2
    k_pack_wih<<<dim3(KIN / 32, G4H / 32), dim3(32, 8)>>>(W_ih);

    // (3) pack W_out -> half2 k-pairs (for the wide GEMM)
    k_pack_wout<<<(int)((256L * 8000 + 255) / 256), 256>>>(W_out);

    // (4) Gx = lstm_input @ W_ih^T + (b_ih+b_hh)  — fp16 (profiled slot)
    hgemm_k<0><<<dim3(G4H / 128, BT / 128), 256>>>(
        linh, KIN / 2, wihp, 0, G4H, bsum, gx, G4H, KIN);

    // (5) LSTM recurrence — persistent kernel
    lstm_persist_k<<<128, 256, (8192 + 8192 + 4096) * sizeof(float)>>>(
        xlen, W_hh, out + OUT0, wo);

    // (6) pack W_att -> [AIN/2][S] half2
    k_packB<<<(int)(((long)(AIN / 2) * Ss + 255) / 256), 256>>>(W_att, wattp_w, AIN / 2, Ss);

    // (7) att logits = attn_in @ W_att + b_att  — fp16
    hgemm_k<0><<<dim3(Ss / 128, BT / 128), 256>>>(
        attnh, AIN / 2, wattp, 0, Ss, b_att, att, Ss, AIN);

    // (8) softmax rows (+half output)
    softmax_k<<<BT, 256>>>();

    // (9) pack encoder (direction-summed) -> [16][S/2][H] half2
    k_pack_enc<<<(int)(((long)Bb * (Ss / 2) * Hh + 255) / 256), 256>>>(eo);

    // (10) h_t_bar = soft @ enc  — fp16 batched (B per y-tile)
    hgemm_k<1><<<dim3(Hh / 128, BT / 128), 256>>>(
        softh, Ss / 2, encp, (long)(Ss / 2) * Hh, Hh, nullptr,
        lohtb + 512, 1024, Ss);

    // (11) pack W_align -> [1024/2][H] half2
    k_packB<<<(int)(((long)512 * Hh + 255) / 256), 256>>>(W_align, walignp_w, 512, Hh);

    // (12) align GEMM + fused combine -> g_Ap half2
    hgemm_k<2><<<dim3(Hh / 128, BT / 128), 256>>>(
        lohh, 512, walignp, 0, Hh, b_align, nullptr, 0, 1024);

    // (13) out = out_pre @ W_out + b_out  — fp16 wide GEMM
    tgemm_wide_h_k<<<dim3(Vv / 256, BT / 128), 256, HSMEM_BYTES>>>(b_out, out);
}